// round 2
// baseline (speedup 1.0000x reference)
#include <cuda_runtime.h>
#include <math.h>

#define BB 64
#define SS 2048
#define HH 1024
#define NSPLIT 8
#define SCHUNK (SS / NSPLIT)   // 256

// ---------------- scratch (no allocations allowed) ----------------
__device__ float g_scores[BB * SS];            // raw attention scores
__device__ float g_pacc[BB * NSPLIT * HH];     // partial weighted sums
__device__ float g_pm[BB * NSPLIT];            // partial running max
__device__ float g_pl[BB * NSPLIT];            // partial exp-sum
__device__ float g_attn[BB * HH];              // combined attention output
__device__ float g_fc1_part[8 * BB * HH];      // fc1 split-K partials
__device__ float g_y[BB * HH];                 // post-BN-tanh activations
__device__ float g_fc2_part[4 * BB * HH];      // fc2 split-K partials

// ================= Kernel 1: single-pass attention (online softmax) =========
// grid (NSPLIT, B), block 256. Each CTA streams 256 rows of ctx[:,b,:] once.
__global__ __launch_bounds__(256) void attn_pass(
    const float* __restrict__ ctx, const float* __restrict__ key,
    const float* __restrict__ mask)
{
    const int b = blockIdx.y;
    const int split = blockIdx.x;
    const int tid = threadIdx.x;
    const int s0 = split * SCHUNK;

    __shared__ float red[4][8];

    const float4* ctx4 = (const float4*)ctx;
    const float4 k4 = ((const float4*)key)[b * (HH / 4) + tid];

    float acc0 = 0.f, acc1 = 0.f, acc2 = 0.f, acc3 = 0.f;
    float m = -1e30f, l = 0.f;

    for (int sb = 0; sb < SCHUNK; sb += 4) {
        float4 r[4];
        float d[4];
#pragma unroll
        for (int i = 0; i < 4; i++) {
            const int s = s0 + sb + i;
            r[i] = ctx4[(size_t)(s * BB + b) * (HH / 4) + tid];
            d[i] = r[i].x * k4.x + r[i].y * k4.y + r[i].z * k4.z + r[i].w * k4.w;
        }
        // warp reduce 4 dots
#pragma unroll
        for (int off = 16; off > 0; off >>= 1) {
#pragma unroll
            for (int i = 0; i < 4; i++)
                d[i] += __shfl_xor_sync(0xffffffffu, d[i], off);
        }
        __syncthreads();  // previous iteration's red reads done
        if ((tid & 31) == 0) {
#pragma unroll
            for (int i = 0; i < 4; i++) red[i][tid >> 5] = d[i];
        }
        __syncthreads();
        float sc[4];
#pragma unroll
        for (int i = 0; i < 4; i++) {
            float t = 0.f;
#pragma unroll
            for (int w = 0; w < 8; w++) t += red[i][w];
            sc[i] = t + mask[b * SS + s0 + sb + i];
        }
        if (tid < 4) g_scores[b * SS + s0 + sb + tid] = sc[tid];

#pragma unroll
        for (int i = 0; i < 4; i++) {
            if (sc[i] > m) {
                const float f = __expf(m - sc[i]);
                m = sc[i];
                l *= f;
                acc0 *= f; acc1 *= f; acc2 *= f; acc3 *= f;
            }
            const float p = __expf(sc[i] - m);
            l += p;
            acc0 += p * r[i].x; acc1 += p * r[i].y;
            acc2 += p * r[i].z; acc3 += p * r[i].w;
        }
    }

    ((float4*)g_pacc)[(size_t)(b * NSPLIT + split) * (HH / 4) + tid] =
        make_float4(acc0, acc1, acc2, acc3);
    if (tid == 0) {
        g_pm[b * NSPLIT + split] = m;
        g_pl[b * NSPLIT + split] = l;
    }
}

// ====== Kernel 2: combine split partials -> attn, and normalize At =========
// grid B, block 256
__global__ __launch_bounds__(256) void combine_kernel(float* __restrict__ out_At)
{
    const int b = blockIdx.x;
    const int tid = threadIdx.x;

    float pm[NSPLIT];
    float M = -1e30f;
#pragma unroll
    for (int i = 0; i < NSPLIT; i++) {
        pm[i] = g_pm[b * NSPLIT + i];
        M = fmaxf(M, pm[i]);
    }
    float L = 0.f;
    float f[NSPLIT];
#pragma unroll
    for (int i = 0; i < NSPLIT; i++) {
        f[i] = __expf(pm[i] - M);
        L += f[i] * g_pl[b * NSPLIT + i];
    }
    const float invL = 1.f / L;

    // attention output
    float4 a = make_float4(0.f, 0.f, 0.f, 0.f);
#pragma unroll
    for (int i = 0; i < NSPLIT; i++) {
        const float4 v =
            ((const float4*)g_pacc)[(size_t)(b * NSPLIT + i) * (HH / 4) + tid];
        a.x += f[i] * v.x; a.y += f[i] * v.y;
        a.z += f[i] * v.z; a.w += f[i] * v.w;
    }
    a.x *= invL; a.y *= invL; a.z *= invL; a.w *= invL;
    ((float4*)g_attn)[b * (HH / 4) + tid] = a;

    // normalized At
    for (int s = tid; s < SS; s += 256)
        out_At[b * SS + s] = __expf(g_scores[b * SS + s] - M) * invL;
}

// ============ Kernel 3/5: split-K GEMM  out[b,j] = sum_k A[b,k]*W[j,k] ======
// block = 256 threads (16x16), tile: 64 b x 64 j x 256 k per CTA.
// A and the partial buffer are device globals, selected at compile time —
// __device__ symbols must NOT be passed as args from host code.
template <int K, bool CAT>
__global__ __launch_bounds__(256) void gemm_splitk(
    const float* __restrict__ key, const float* __restrict__ W)
{
    const float* A  = CAT ? g_attn : g_y;
    float* part     = CAT ? g_fc1_part : g_fc2_part;

    const int tid = threadIdx.x;
    const int j0 = blockIdx.x * 64;
    const int k0 = blockIdx.y * 256;
    const int tx = tid & 15, ty = tid >> 4;

    __shared__ float As[64][33];
    __shared__ float Ws[64][33];

    float acc[4][4];
#pragma unroll
    for (int i = 0; i < 4; i++)
#pragma unroll
        for (int j = 0; j < 4; j++) acc[i][j] = 0.f;

    for (int kk = 0; kk < 256; kk += 32) {
#pragma unroll
        for (int t = 0; t < 8; t++) {
            const int e = tid + t * 256;
            const int r = e >> 5, c = e & 31;
            const int kg = k0 + kk + c;
            float av;
            if (CAT)
                av = (kg < HH) ? A[r * HH + kg] : key[r * HH + kg - HH];
            else
                av = A[r * K + kg];
            As[r][c] = av;
            Ws[r][c] = W[(size_t)(j0 + r) * K + kg];
        }
        __syncthreads();
#pragma unroll
        for (int k = 0; k < 32; k++) {
            float av[4], wv[4];
#pragma unroll
            for (int bi = 0; bi < 4; bi++) av[bi] = As[ty * 4 + bi][k];
#pragma unroll
            for (int ji = 0; ji < 4; ji++) wv[ji] = Ws[tx * 4 + ji][k];
#pragma unroll
            for (int bi = 0; bi < 4; bi++)
#pragma unroll
                for (int ji = 0; ji < 4; ji++) acc[bi][ji] += av[bi] * wv[ji];
        }
        __syncthreads();
    }

#pragma unroll
    for (int bi = 0; bi < 4; bi++) {
#pragma unroll
        for (int ji = 0; ji < 4; ji++) {
            const int b = ty * 4 + bi;
            const int j = j0 + tx * 4 + ji;
            part[(size_t)(blockIdx.y * BB + b) * HH + j] = acc[bi][ji];
        }
    }
}

// ======== Kernel 4: reduce fc1 partials + BatchNorm(train) + tanh ==========
// 1024 threads total (grid 4 x 256): one thread per feature j.
// fc1_b is skipped: any per-feature constant cancels exactly in (x - mean).
__global__ __launch_bounds__(256) void bn_tanh_kernel(
    const float* __restrict__ gamma, const float* __restrict__ beta)
{
    const int j = blockIdx.x * 256 + threadIdx.x;
    float xv[BB];
#pragma unroll
    for (int b = 0; b < BB; b++) {
        float s = 0.f;
#pragma unroll
        for (int sp = 0; sp < 8; sp++)
            s += g_fc1_part[(size_t)(sp * BB + b) * HH + j];
        xv[b] = s;
    }
    float mean = 0.f;
#pragma unroll
    for (int b = 0; b < BB; b++) mean += xv[b];
    mean *= (1.f / BB);
    float var = 0.f;
#pragma unroll
    for (int b = 0; b < BB; b++) {
        const float d = xv[b] - mean;
        var += d * d;
    }
    var *= (1.f / BB);
    const float inv = rsqrtf(var + 1e-5f);
    const float g = gamma[j], be = beta[j];
#pragma unroll
    for (int b = 0; b < BB; b++)
        g_y[b * HH + j] = tanhf((xv[b] - mean) * inv * g + be);
}

// ======== Kernel 6: reduce fc2 partials + bias -> output x ==================
__global__ __launch_bounds__(256) void finalize_kernel(
    const float* __restrict__ fc2_b, float* __restrict__ out_x)
{
    const int idx = blockIdx.x * 256 + threadIdx.x;  // 65536 total
    const int j = idx & (HH - 1);
    float v = fc2_b[j];
#pragma unroll
    for (int kt = 0; kt < 4; kt++)
        v += g_fc2_part[(size_t)kt * BB * HH + idx];
    out_x[idx] = v;
}

// ============================ launch ========================================
extern "C" void kernel_launch(void* const* d_in, const int* in_sizes, int n_in,
                              void* d_out, int out_size)
{
    const float* ctx   = (const float*)d_in[0];
    const float* key   = (const float*)d_in[1];
    const float* mask  = (const float*)d_in[2];
    const float* fc1_w = (const float*)d_in[3];
    // d_in[4] = fc1_b (cancels in BatchNorm, unused)
    const float* bn_g  = (const float*)d_in[5];
    const float* bn_b  = (const float*)d_in[6];
    const float* fc2_w = (const float*)d_in[7];
    const float* fc2_b = (const float*)d_in[8];

    float* out_x  = (float*)d_out;              // (B, H)  = 65536 floats
    float* out_At = (float*)d_out + BB * HH;    // (B, S)  = 131072 floats

    attn_pass<<<dim3(NSPLIT, BB), 256>>>(ctx, key, mask);
    combine_kernel<<<BB, 256>>>(out_At);

    // fc1: cat([attn, key]) @ fc1_w.T   (K = 2048, 8 k-splits)
    gemm_splitk<2048, true><<<dim3(16, 8), 256>>>(key, fc1_w);
    bn_tanh_kernel<<<4, 256>>>(bn_g, bn_b);

    // fc2: y @ fc2_w.T                  (K = 1024, 4 k-splits)
    gemm_splitk<1024, false><<<dim3(16, 4), 256>>>(key, fc2_w);
    finalize_kernel<<<256, 256>>>(fc2_b, out_x);
}

// round 3
// speedup vs baseline: 1.1914x; 1.1914x over previous
#include <cuda_runtime.h>
#include <math.h>

#define BB 64
#define SS 2048
#define HH 1024
#define CTAS_PER_B 4
#define WARPS_PER_CTA 8
#define SPLITS (CTAS_PER_B * WARPS_PER_CTA)   // 32
#define ROWS_PER_WARP (SS / SPLITS)           // 64

// ---------------- scratch (no allocations allowed) ----------------
__device__ float g_scores[BB * SS];             // raw attention scores
__device__ float g_pacc[BB * SPLITS * HH];      // partial weighted sums (8 MB)
__device__ float g_pm[BB * SPLITS];             // partial running max
__device__ float g_pl[BB * SPLITS];             // partial exp-sum
__device__ float g_attn[BB * HH];               // combined attention output
__device__ float g_fc1_part[8 * BB * HH];       // fc1 split-K partials
__device__ float g_y[BB * HH];                  // post-BN-tanh activations
__device__ float g_fc2_part[4 * BB * HH];       // fc2 split-K partials

// ================= Kernel 1: warp-per-row attention (online softmax) ========
// grid (CTAS_PER_B, B), block 256 = 8 independent warps.
// Each warp streams ROWS_PER_WARP rows of ctx[:, b, :] exactly once.
__global__ __launch_bounds__(256) void attn_pass(
    const float* __restrict__ ctx, const float* __restrict__ key,
    const float* __restrict__ mask)
{
    const int b    = blockIdx.y;
    const int w    = threadIdx.x >> 5;
    const int lane = threadIdx.x & 31;
    const int split = blockIdx.x * WARPS_PER_CTA + w;
    const int s0    = split * ROWS_PER_WARP;

    const float4* ctx4 = (const float4*)ctx;
    const float4* key4 = (const float4*)key;

    // persistent key slice: 8 float4 = this lane's 32 of 1024 H-elements
    float4 kk[8];
#pragma unroll
    for (int j = 0; j < 8; j++)
        kk[j] = key4[b * (HH / 4) + j * 32 + lane];

    float4 acc[8];
#pragma unroll
    for (int j = 0; j < 8; j++) acc[j] = make_float4(0.f, 0.f, 0.f, 0.f);
    float m = -1e30f, l = 0.f;

    for (int r = 0; r < ROWS_PER_WARP; r++) {
        const int s = s0 + r;
        const float4* row = ctx4 + (size_t)(s * BB + b) * (HH / 4);
        float4 rv[8];
#pragma unroll
        for (int j = 0; j < 8; j++) rv[j] = row[j * 32 + lane];

        float d = 0.f;
#pragma unroll
        for (int j = 0; j < 8; j++)
            d += rv[j].x * kk[j].x + rv[j].y * kk[j].y +
                 rv[j].z * kk[j].z + rv[j].w * kk[j].w;
#pragma unroll
        for (int off = 16; off > 0; off >>= 1)
            d += __shfl_xor_sync(0xffffffffu, d, off);

        d += mask[b * SS + s];
        if (lane == 0) g_scores[b * SS + s] = d;

        if (d > m) {
            const float f = __expf(m - d);
            m = d;
            l *= f;
#pragma unroll
            for (int j = 0; j < 8; j++) {
                acc[j].x *= f; acc[j].y *= f; acc[j].z *= f; acc[j].w *= f;
            }
        }
        const float p = __expf(d - m);
        l += p;
#pragma unroll
        for (int j = 0; j < 8; j++) {
            acc[j].x += p * rv[j].x; acc[j].y += p * rv[j].y;
            acc[j].z += p * rv[j].z; acc[j].w += p * rv[j].w;
        }
    }

    float4* pacc4 = (float4*)g_pacc;
#pragma unroll
    for (int j = 0; j < 8; j++)
        pacc4[(size_t)(b * SPLITS + split) * (HH / 4) + j * 32 + lane] = acc[j];
    if (lane == 0) {
        g_pm[b * SPLITS + split] = m;
        g_pl[b * SPLITS + split] = l;
    }
}

// ====== Kernel 2: combine split partials -> attn, and normalize At =========
// grid B, block 256
__global__ __launch_bounds__(256) void combine_kernel(float* __restrict__ out_At)
{
    const int b = blockIdx.x;
    const int tid = threadIdx.x;

    float M = -1e30f;
#pragma unroll
    for (int i = 0; i < SPLITS; i++)
        M = fmaxf(M, g_pm[b * SPLITS + i]);

    float L = 0.f;
    float4 a = make_float4(0.f, 0.f, 0.f, 0.f);
#pragma unroll
    for (int i = 0; i < SPLITS; i++) {
        const float f = __expf(g_pm[b * SPLITS + i] - M);
        L += f * g_pl[b * SPLITS + i];
        const float4 v =
            ((const float4*)g_pacc)[(size_t)(b * SPLITS + i) * (HH / 4) + tid];
        a.x += f * v.x; a.y += f * v.y; a.z += f * v.z; a.w += f * v.w;
    }
    const float invL = 1.f / L;
    a.x *= invL; a.y *= invL; a.z *= invL; a.w *= invL;
    ((float4*)g_attn)[b * (HH / 4) + tid] = a;

    for (int s = tid; s < SS; s += 256)
        out_At[b * SS + s] = __expf(g_scores[b * SS + s] - M) * invL;
}

// ============ Kernel 3/5: split-K GEMM  out[b,j] = sum_k A[b,k]*W[j,k] ======
// block = 256 threads (16x16), tile: 64 b x 64 j x 256 k per CTA.
// Scratch arrays are device globals selected at compile time.
template <int K, bool CAT>
__global__ __launch_bounds__(256) void gemm_splitk(
    const float* __restrict__ key, const float* __restrict__ W)
{
    const float* A  = CAT ? g_attn : g_y;
    float* part     = CAT ? g_fc1_part : g_fc2_part;

    const int tid = threadIdx.x;
    const int j0 = blockIdx.x * 64;
    const int k0 = blockIdx.y * 256;
    const int tx = tid & 15, ty = tid >> 4;

    __shared__ float As[64][33];
    __shared__ float Ws[64][33];

    float acc[4][4];
#pragma unroll
    for (int i = 0; i < 4; i++)
#pragma unroll
        for (int j = 0; j < 4; j++) acc[i][j] = 0.f;

    for (int kk = 0; kk < 256; kk += 32) {
#pragma unroll
        for (int t = 0; t < 8; t++) {
            const int e = tid + t * 256;
            const int r = e >> 5, c = e & 31;
            const int kg = k0 + kk + c;
            float av;
            if (CAT)
                av = (kg < HH) ? A[r * HH + kg] : key[r * HH + kg - HH];
            else
                av = A[r * K + kg];
            As[r][c] = av;
            Ws[r][c] = W[(size_t)(j0 + r) * K + kg];
        }
        __syncthreads();
#pragma unroll
        for (int k = 0; k < 32; k++) {
            float av[4], wv[4];
#pragma unroll
            for (int bi = 0; bi < 4; bi++) av[bi] = As[ty * 4 + bi][k];
#pragma unroll
            for (int ji = 0; ji < 4; ji++) wv[ji] = Ws[tx * 4 + ji][k];
#pragma unroll
            for (int bi = 0; bi < 4; bi++)
#pragma unroll
                for (int ji = 0; ji < 4; ji++) acc[bi][ji] += av[bi] * wv[ji];
        }
        __syncthreads();
    }

#pragma unroll
    for (int bi = 0; bi < 4; bi++) {
#pragma unroll
        for (int ji = 0; ji < 4; ji++) {
            const int b = ty * 4 + bi;
            const int j = j0 + tx * 4 + ji;
            part[(size_t)(blockIdx.y * BB + b) * HH + j] = acc[bi][ji];
        }
    }
}

// ======== Kernel 4: reduce fc1 partials + BatchNorm(train) + tanh ==========
// grid 16 x 256: block handles 64 features x all 64 batches, coalesced in j.
// fc1_b is skipped: any per-feature constant cancels exactly in (x - mean).
__global__ __launch_bounds__(256) void bn_tanh_kernel(
    const float* __restrict__ gamma, const float* __restrict__ beta)
{
    __shared__ float sx[BB][64];      // [batch][feature-local], 16 KB
    __shared__ float rsum[4][64];
    __shared__ float rsq[4][64];

    const int t  = threadIdx.x;
    const int jl = t & 63;
    const int bt = t >> 6;            // 0..3, each covers 16 batches
    const int j  = blockIdx.x * 64 + jl;

    float ps = 0.f, pq = 0.f;
#pragma unroll
    for (int bi = 0; bi < 16; bi++) {
        const int b = bt * 16 + bi;
        float s = 0.f;
#pragma unroll
        for (int sp = 0; sp < 8; sp++)
            s += g_fc1_part[((size_t)sp * BB + b) * HH + j];
        sx[b][jl] = s;
        ps += s;
        pq += s * s;
    }
    rsum[bt][jl] = ps;
    rsq[bt][jl]  = pq;
    __syncthreads();

    const float mean = (rsum[0][jl] + rsum[1][jl] + rsum[2][jl] + rsum[3][jl])
                       * (1.f / BB);
    const float msq  = (rsq[0][jl] + rsq[1][jl] + rsq[2][jl] + rsq[3][jl])
                       * (1.f / BB);
    const float var  = msq - mean * mean;
    const float inv  = rsqrtf(var + 1e-5f);
    const float g    = gamma[j] * inv;
    const float be   = beta[j] - mean * g;

#pragma unroll
    for (int bi = 0; bi < 16; bi++) {
        const int b = bt * 16 + bi;
        g_y[b * HH + j] = tanhf(sx[b][jl] * g + be);
    }
}

// ======== Kernel 6: reduce fc2 partials + bias -> output x ==================
__global__ __launch_bounds__(256) void finalize_kernel(
    const float* __restrict__ fc2_b, float* __restrict__ out_x)
{
    const int idx = blockIdx.x * 256 + threadIdx.x;  // 65536 total
    const int j = idx & (HH - 1);
    float v = fc2_b[j];
#pragma unroll
    for (int kt = 0; kt < 4; kt++)
        v += g_fc2_part[(size_t)kt * BB * HH + idx];
    out_x[idx] = v;
}

// ============================ launch ========================================
extern "C" void kernel_launch(void* const* d_in, const int* in_sizes, int n_in,
                              void* d_out, int out_size)
{
    const float* ctx   = (const float*)d_in[0];
    const float* key   = (const float*)d_in[1];
    const float* mask  = (const float*)d_in[2];
    const float* fc1_w = (const float*)d_in[3];
    // d_in[4] = fc1_b (cancels in BatchNorm, unused)
    const float* bn_g  = (const float*)d_in[5];
    const float* bn_b  = (const float*)d_in[6];
    const float* fc2_w = (const float*)d_in[7];
    const float* fc2_b = (const float*)d_in[8];

    float* out_x  = (float*)d_out;              // (B, H)  = 65536 floats
    float* out_At = (float*)d_out + BB * HH;    // (B, S)  = 131072 floats

    attn_pass<<<dim3(CTAS_PER_B, BB), 256>>>(ctx, key, mask);
    combine_kernel<<<BB, 256>>>(out_At);

    // fc1: cat([attn, key]) @ fc1_w.T   (K = 2048, 8 k-splits)
    gemm_splitk<2048, true><<<dim3(16, 8), 256>>>(key, fc1_w);
    bn_tanh_kernel<<<16, 256>>>(bn_g, bn_b);

    // fc2: y @ fc2_w.T                  (K = 1024, 4 k-splits)
    gemm_splitk<1024, false><<<dim3(16, 4), 256>>>(key, fc2_w);
    finalize_kernel<<<256, 256>>>(fc2_b, out_x);
}

// round 4
// speedup vs baseline: 1.2960x; 1.0878x over previous
#include <cuda_runtime.h>
#include <math.h>

#define BB 64
#define SS 2048
#define HH 1024
#define CTAS_PER_B 4
#define WARPS_PER_CTA 8
#define SPLITS (CTAS_PER_B * WARPS_PER_CTA)   // 32
#define ROWS_PER_WARP (SS / SPLITS)           // 64

// ---------------- scratch (no allocations allowed) ----------------
__device__ float g_scores[BB * SS];             // raw attention scores
__device__ float g_pacc[BB * SPLITS * HH];      // partial weighted sums (8 MB)
__device__ float g_pm[BB * SPLITS];             // partial running max
__device__ float g_pl[BB * SPLITS];             // partial exp-sum
__device__ float g_attn[BB * HH];               // combined attention output
__device__ float g_fc1_part[8 * BB * HH];       // fc1 split-K partials
__device__ float g_y[BB * HH];                  // post-BN-tanh activations
__device__ float g_fc2_part[8 * BB * HH];       // fc2 split-K partials

// ================= Kernel 1: warp-per-row attention (online softmax) ========
// grid (CTAS_PER_B, B), block 256 = 8 independent warps.
// Each warp streams ROWS_PER_WARP rows of ctx[:, b, :] exactly once.
__global__ __launch_bounds__(256) void attn_pass(
    const float* __restrict__ ctx, const float* __restrict__ key,
    const float* __restrict__ mask)
{
    const int b    = blockIdx.y;
    const int w    = threadIdx.x >> 5;
    const int lane = threadIdx.x & 31;
    const int split = blockIdx.x * WARPS_PER_CTA + w;
    const int s0    = split * ROWS_PER_WARP;

    const float4* ctx4 = (const float4*)ctx;
    const float4* key4 = (const float4*)key;

    float4 kk[8];
#pragma unroll
    for (int j = 0; j < 8; j++)
        kk[j] = key4[b * (HH / 4) + j * 32 + lane];

    float4 acc[8];
#pragma unroll
    for (int j = 0; j < 8; j++) acc[j] = make_float4(0.f, 0.f, 0.f, 0.f);
    float m = -1e30f, l = 0.f;

    for (int r = 0; r < ROWS_PER_WARP; r++) {
        const int s = s0 + r;
        const float4* row = ctx4 + (size_t)(s * BB + b) * (HH / 4);
        float4 rv[8];
#pragma unroll
        for (int j = 0; j < 8; j++) rv[j] = row[j * 32 + lane];

        float d = 0.f;
#pragma unroll
        for (int j = 0; j < 8; j++)
            d += rv[j].x * kk[j].x + rv[j].y * kk[j].y +
                 rv[j].z * kk[j].z + rv[j].w * kk[j].w;
#pragma unroll
        for (int off = 16; off > 0; off >>= 1)
            d += __shfl_xor_sync(0xffffffffu, d, off);

        d += mask[b * SS + s];
        if (lane == 0) g_scores[b * SS + s] = d;

        if (d > m) {
            const float f = __expf(m - d);
            m = d;
            l *= f;
#pragma unroll
            for (int j = 0; j < 8; j++) {
                acc[j].x *= f; acc[j].y *= f; acc[j].z *= f; acc[j].w *= f;
            }
        }
        const float p = __expf(d - m);
        l += p;
#pragma unroll
        for (int j = 0; j < 8; j++) {
            acc[j].x += p * rv[j].x; acc[j].y += p * rv[j].y;
            acc[j].z += p * rv[j].z; acc[j].w += p * rv[j].w;
        }
    }

    float4* pacc4 = (float4*)g_pacc;
#pragma unroll
    for (int j = 0; j < 8; j++)
        pacc4[(size_t)(b * SPLITS + split) * (HH / 4) + j * 32 + lane] = acc[j];
    if (lane == 0) {
        g_pm[b * SPLITS + split] = m;
        g_pl[b * SPLITS + split] = l;
    }
}

// ====== Kernel 2: combine split partials -> attn | normalize At ============
// grid (B, 2), block 256. phase 0: attn combine. phase 1: At normalize.
__global__ __launch_bounds__(256) void combine_kernel(float* __restrict__ out_At)
{
    const int b = blockIdx.x;
    const int tid = threadIdx.x;

    float M = -1e30f;
#pragma unroll
    for (int i = 0; i < SPLITS; i++)
        M = fmaxf(M, g_pm[b * SPLITS + i]);
    float L = 0.f;
#pragma unroll
    for (int i = 0; i < SPLITS; i++)
        L += __expf(g_pm[b * SPLITS + i] - M) * g_pl[b * SPLITS + i];
    const float invL = 1.f / L;

    if (blockIdx.y == 0) {
        float4 a = make_float4(0.f, 0.f, 0.f, 0.f);
#pragma unroll
        for (int i = 0; i < SPLITS; i++) {
            const float f = __expf(g_pm[b * SPLITS + i] - M);
            const float4 v =
                ((const float4*)g_pacc)[(size_t)(b * SPLITS + i) * (HH / 4) + tid];
            a.x += f * v.x; a.y += f * v.y; a.z += f * v.z; a.w += f * v.w;
        }
        a.x *= invL; a.y *= invL; a.z *= invL; a.w *= invL;
        ((float4*)g_attn)[b * (HH / 4) + tid] = a;
    } else {
        const float4* sc4 = (const float4*)(g_scores + b * SS);
        float4* at4 = (float4*)(out_At + b * SS);
#pragma unroll
        for (int it = 0; it < SS / 4 / 256; it++) {
            const float4 s = sc4[it * 256 + tid];
            at4[it * 256 + tid] = make_float4(
                __expf(s.x - M) * invL, __expf(s.y - M) * invL,
                __expf(s.z - M) * invL, __expf(s.w - M) * invL);
        }
    }
}

// ============ Kernel 3/5: split-K GEMM  out[b,j] = sum_k A[b,k]*W[j,k] ======
// block = 256 threads (16x16), tile: 64 b x 64 j x KCHUNK k per CTA.
template <int K, int KCHUNK, bool CAT>
__global__ __launch_bounds__(256) void gemm_splitk(
    const float* __restrict__ key, const float* __restrict__ W)
{
    const float* A  = CAT ? g_attn : g_y;
    float* part     = CAT ? g_fc1_part : g_fc2_part;

    const int tid = threadIdx.x;
    const int j0 = blockIdx.x * 64;
    const int k0 = blockIdx.y * KCHUNK;
    const int tx = tid & 15, ty = tid >> 4;

    __shared__ float As[64][33];
    __shared__ float Ws[64][33];

    float acc[4][4];
#pragma unroll
    for (int i = 0; i < 4; i++)
#pragma unroll
        for (int j = 0; j < 4; j++) acc[i][j] = 0.f;

    for (int kk = 0; kk < KCHUNK; kk += 32) {
#pragma unroll
        for (int t = 0; t < 8; t++) {
            const int e = tid + t * 256;
            const int r = e >> 5, c = e & 31;
            const int kg = k0 + kk + c;
            float av;
            if (CAT)
                av = (kg < HH) ? A[r * HH + kg] : key[r * HH + kg - HH];
            else
                av = A[r * K + kg];
            As[r][c] = av;
            Ws[r][c] = W[(size_t)(j0 + r) * K + kg];
        }
        __syncthreads();
#pragma unroll
        for (int k = 0; k < 32; k++) {
            float av[4], wv[4];
#pragma unroll
            for (int bi = 0; bi < 4; bi++) av[bi] = As[ty * 4 + bi][k];
#pragma unroll
            for (int ji = 0; ji < 4; ji++) wv[ji] = Ws[tx * 4 + ji][k];
#pragma unroll
            for (int bi = 0; bi < 4; bi++)
#pragma unroll
                for (int ji = 0; ji < 4; ji++) acc[bi][ji] += av[bi] * wv[ji];
        }
        __syncthreads();
    }

#pragma unroll
    for (int bi = 0; bi < 4; bi++) {
#pragma unroll
        for (int ji = 0; ji < 4; ji++) {
            const int b = ty * 4 + bi;
            const int j = j0 + tx * 4 + ji;
            part[(size_t)(blockIdx.y * BB + b) * HH + j] = acc[bi][ji];
        }
    }
}

// ======== Kernel 4: reduce fc1 partials + BatchNorm(train) + tanh ==========
// grid 64, block 256: CTA = 16 features x 64 batches. 4 batches/thread-group.
// fc1_b is skipped: any per-feature constant cancels exactly in (x - mean).
__global__ __launch_bounds__(256) void bn_tanh_kernel(
    const float* __restrict__ gamma, const float* __restrict__ beta)
{
    __shared__ float sx[BB][17];      // [batch][feature-local], padded
    __shared__ float rsum[16][17];
    __shared__ float rsq[16][17];

    const int t  = threadIdx.x;
    const int jl = t & 15;
    const int bt = t >> 4;            // 0..15, each covers 4 batches
    const int j  = blockIdx.x * 16 + jl;

    float ps = 0.f, pq = 0.f;
#pragma unroll
    for (int bi = 0; bi < 4; bi++) {
        const int b = bt * 4 + bi;
        float s = 0.f;
#pragma unroll
        for (int sp = 0; sp < 8; sp++)
            s += g_fc1_part[((size_t)sp * BB + b) * HH + j];
        sx[b][jl] = s;
        ps += s;
        pq += s * s;
    }
    rsum[bt][jl] = ps;
    rsq[bt][jl]  = pq;
    __syncthreads();

    float mean = 0.f, msq = 0.f;
#pragma unroll
    for (int g = 0; g < 16; g++) {
        mean += rsum[g][jl];
        msq  += rsq[g][jl];
    }
    mean *= (1.f / BB);
    msq  *= (1.f / BB);
    const float var = msq - mean * mean;
    const float inv = rsqrtf(var + 1e-5f);
    const float gm  = gamma[j] * inv;
    const float be  = beta[j] - mean * gm;

#pragma unroll
    for (int bi = 0; bi < 4; bi++) {
        const int b = bt * 4 + bi;
        g_y[b * HH + j] = tanhf(sx[b][jl] * gm + be);
    }
}

// ======== Kernel 6: reduce fc2 partials + bias -> output x ==================
__global__ __launch_bounds__(256) void finalize_kernel(
    const float* __restrict__ fc2_b, float* __restrict__ out_x)
{
    const int idx = blockIdx.x * 256 + threadIdx.x;  // 65536 total
    const int j = idx & (HH - 1);
    float v = fc2_b[j];
#pragma unroll
    for (int kt = 0; kt < 8; kt++)
        v += g_fc2_part[(size_t)kt * BB * HH + idx];
    out_x[idx] = v;
}

// ============================ launch ========================================
extern "C" void kernel_launch(void* const* d_in, const int* in_sizes, int n_in,
                              void* d_out, int out_size)
{
    const float* ctx   = (const float*)d_in[0];
    const float* key   = (const float*)d_in[1];
    const float* mask  = (const float*)d_in[2];
    const float* fc1_w = (const float*)d_in[3];
    // d_in[4] = fc1_b (cancels in BatchNorm, unused)
    const float* bn_g  = (const float*)d_in[5];
    const float* bn_b  = (const float*)d_in[6];
    const float* fc2_w = (const float*)d_in[7];
    const float* fc2_b = (const float*)d_in[8];

    float* out_x  = (float*)d_out;              // (B, H)  = 65536 floats
    float* out_At = (float*)d_out + BB * HH;    // (B, S)  = 131072 floats

    attn_pass<<<dim3(CTAS_PER_B, BB), 256>>>(ctx, key, mask);
    combine_kernel<<<dim3(BB, 2), 256>>>(out_At);

    // fc1: cat([attn, key]) @ fc1_w.T   (K = 2048, 8 k-splits of 256)
    gemm_splitk<2048, 256, true><<<dim3(16, 8), 256>>>(key, fc1_w);
    bn_tanh_kernel<<<64, 256>>>(bn_g, bn_b);

    // fc2: y @ fc2_w.T                  (K = 1024, 8 k-splits of 128)
    gemm_splitk<1024, 128, false><<<dim3(16, 8), 256>>>(key, fc2_w);
    finalize_kernel<<<256, 256>>>(fc2_b, out_x);
}